// round 4
// baseline (speedup 1.0000x reference)
#include <cuda_runtime.h>
#include <cuda_bf16.h>
#include <math.h>

// Problem constants
#define BB   64
#define CC   2048
#define HW   196
#define MM   32
#define NC   396
#define KTOT (MM * CC)          // 65536

// kernel-1 split-K
#define KS1     8
#define CSLICE  (CC / KS1)      // 256

// kernel-3 split-K
#define KS3       64
#define KSLICE3   (KTOT / KS3)  // 1024
#define KCHUNK3   128
#define NTILE3    64
#define NT3       7             // ceil(396/64)

// -------- scratch (device globals; no runtime allocation) --------
__device__ float g_part1[KS1 * BB * MM * HW];     // 12.85 MB: [ks][b][m][hw]
__device__ float g_A    [BB * MM * HW];           //  1.6 MB : [b][m][hw]
__device__ float g_bap  [BB * KTOT];              // 16.0 MB : [b][m*2048+c]
__device__ float g_part3[KS3 * BB * NC];          //  6.5 MB : [ks][b][n]

// -------- packed f32x2 helpers (Blackwell FFMA2 path) --------
__device__ __forceinline__ unsigned long long pk2(float lo, float hi) {
    unsigned long long r;
    asm("mov.b64 %0, {%1, %2};" : "=l"(r) : "f"(lo), "f"(hi));
    return r;
}
__device__ __forceinline__ void fma2(unsigned long long& d,
                                     unsigned long long a,
                                     unsigned long long b) {
    asm("fma.rn.f32x2 %0, %1, %2, %0;" : "+l"(d) : "l"(a), "l"(b));
}
__device__ __forceinline__ void up2(unsigned long long v, float& lo, float& hi) {
    asm("mov.b64 {%0, %1}, %2;" : "=f"(lo), "=f"(hi) : "l"(v));
}
__device__ __forceinline__ float red2(unsigned long long v) {
    float lo, hi; up2(v, lo, hi);
    return lo + hi;
}

// ============================================================================
// Kernel 1: partial attention logits. grid (BB, KS1), block 224 (196 active).
// Thread = 8 m (quarter mq) x 4 hw. Weights staged ONCE per block as
// duplicated {w,w} u64 pairs, pair-swizzled by (+c mod 16) so staging STS is
// conflict-free; compute reads are warp-uniform broadcasts.
// Per c: 1 LDG.128 (x, coalesced) + 4 LDS.128 + 16 fma2.
// ============================================================================
__global__ __launch_bounds__(224) void k1_logits(const float* __restrict__ x,
                                                 const float* __restrict__ Wa) {
    extern __shared__ unsigned long long ws[];   // [CSLICE][32] u64 = 64 KB
    const int b  = blockIdx.x;
    const int ks = blockIdx.y;
    const int t  = threadIdx.x;
    const int c0 = ks * CSLICE;

    // Stage duplicated weights: coalesced LDG (c fastest), swizzled STS.
    for (int idx = t; idx < CSLICE * 32; idx += 224) {
        const int m = idx >> 8;          // 0..31
        const int c = idx & 255;         // 0..CSLICE-1
        const float w = Wa[(size_t)m * CC + c0 + c];
        const int p = m >> 1;            // m-pair index
        ws[c * 32 + 2 * ((p + c) & 15) + (m & 1)] = pk2(w, w);
    }
    __syncthreads();

    if (t >= 196) return;
    const int hwg = t % 49;              // 4-hw group
    const int mq  = t / 49;              // m quarter, 0..3

    unsigned long long acc[8][2];
#pragma unroll
    for (int j = 0; j < 8; ++j) { acc[j][0] = 0ull; acc[j][1] = 0ull; }

    const float* xb = x + ((size_t)b * CC + c0) * HW + 4 * hwg;

#pragma unroll 2
    for (int c = 0; c < CSLICE; ++c) {
        const float4 xv4 = *(const float4*)(xb + (size_t)c * HW);
        const unsigned long long x0 = pk2(xv4.x, xv4.y);
        const unsigned long long x1 = pk2(xv4.z, xv4.w);
        const unsigned long long* wrow = ws + c * 32;
#pragma unroll
        for (int j2 = 0; j2 < 4; ++j2) {
            const int p = 4 * mq + j2;
            const ulonglong2 w =
                *(const ulonglong2*)(wrow + 2 * ((p + c) & 15));
            fma2(acc[2 * j2][0],     x0, w.x);
            fma2(acc[2 * j2][1],     x1, w.x);
            fma2(acc[2 * j2 + 1][0], x0, w.y);
            fma2(acc[2 * j2 + 1][1], x1, w.y);
        }
    }

    const size_t base = ((size_t)ks * BB + b) * (MM * HW);
#pragma unroll
    for (int j = 0; j < 8; ++j) {
        const int m = 8 * mq + j;
        float4 o;
        up2(acc[j][0], o.x, o.y);
        up2(acc[j][1], o.z, o.w);
        *(float4*)(g_part1 + base + (size_t)m * HW + 4 * hwg) = o;
    }
}

// ============================================================================
// Kernel 1b: reduce split-K partials, add bias, sigmoid -> g_A.
// ============================================================================
__global__ __launch_bounds__(256) void k1b_sigmoid(const float* __restrict__ ba) {
    const int i = blockIdx.x * 256 + threadIdx.x;
    const int m = (i / HW) & (MM - 1);
    float z = ba[m];
#pragma unroll
    for (int s = 0; s < KS1; ++s)
        z += g_part1[(size_t)s * (BB * MM * HW) + i];
    g_A[i] = 1.0f / (1.0f + expf(-z));
}

// ============================================================================
// Kernel 2: BAP pooling. grid (32 c-tiles, 64 b), block 128.
// Thread tile 4c x 4m, c strided (cg + 16i) so each x-LDS is exactly 2
// conflict-free wavefronts; a-loads are broadcasts.
// Per h4 (4 hw): 8 LDS.128, 32 fma2.
// ============================================================================
__global__ __launch_bounds__(128) void k2_bap(const float* __restrict__ x) {
    extern __shared__ float sm2[];
    float* xs  = sm2;                 // [64][196]
    float* as_ = sm2 + 64 * HW;       // [32][196]

    const int b  = blockIdx.y;
    const int c0 = blockIdx.x * 64;
    const int t  = threadIdx.x;

    {
        const float4* xsrc = (const float4*)(x + ((size_t)b * CC + c0) * HW);
        float4* xd = (float4*)xs;
        for (int i = t; i < 64 * (HW / 4); i += 128) xd[i] = xsrc[i];
        const float4* asrc = (const float4*)(g_A + (size_t)b * (MM * HW));
        float4* ad = (float4*)as_;
        for (int i = t; i < 32 * (HW / 4); i += 128) ad[i] = asrc[i];
    }
    __syncthreads();

    const int cg = t & 15;     // c = c0 + cg + 16*i
    const int mg = t >> 4;     // m = 4*mg + j

    unsigned long long acc[4][4];
#pragma unroll
    for (int i = 0; i < 4; ++i)
#pragma unroll
        for (int j = 0; j < 4; ++j) acc[i][j] = 0ull;

    const ulonglong2* xu = (const ulonglong2*)xs;   // row stride 49 u2
    const ulonglong2* au = (const ulonglong2*)as_;

#pragma unroll 7
    for (int h4 = 0; h4 < HW / 4; ++h4) {
        ulonglong2 xv[4];
#pragma unroll
        for (int i = 0; i < 4; ++i)
            xv[i] = xu[(cg + 16 * i) * 49 + h4];
#pragma unroll
        for (int j = 0; j < 4; ++j) {
            const ulonglong2 av = au[(4 * mg + j) * 49 + h4];
#pragma unroll
            for (int i = 0; i < 4; ++i) {
                fma2(acc[i][j], xv[i].x, av.x);
                fma2(acc[i][j], xv[i].y, av.y);
            }
        }
    }

    const float inv = 1.0f / 196.0f;
#pragma unroll
    for (int i = 0; i < 4; ++i) {
        const int c = c0 + cg + 16 * i;
#pragma unroll
        for (int j = 0; j < 4; ++j) {
            const int m = 4 * mg + j;
            g_bap[(size_t)b * KTOT + (size_t)m * CC + c] = red2(acc[i][j]) * inv;
        }
    }
}

// ============================================================================
// Kernel 3: classifier GEMM partials. grid (KS3, NT3), block 128.
// Tile 64b x 64n, thread tile 8b x 4n (n = n0 + ng + 16j).
// Per k4 (4 k): 12 LDS.128 (all broadcast wavefronts), 64 fma2.
// ============================================================================
__global__ __launch_bounds__(128) void k3_gemm(const float* __restrict__ Wc) {
    extern __shared__ float sm3[];
    float* baps = sm3;                 // [64][132]
    float* wcs  = sm3 + 64 * 132;      // [64][132]

    const int ks = blockIdx.x;
    const int n0 = blockIdx.y * NTILE3;
    const int t  = threadIdx.x;
    const int bg = t & 7;
    const int ng = t >> 3;             // 0..15, n = n0 + ng + 16*j

    unsigned long long acc[8][4];
#pragma unroll
    for (int i = 0; i < 8; ++i)
#pragma unroll
        for (int j = 0; j < 4; ++j) acc[i][j] = 0ull;

    const size_t kbase0 = (size_t)ks * KSLICE3;

    for (int ch = 0; ch < KSLICE3 / KCHUNK3; ++ch) {
        const size_t kb = kbase0 + (size_t)ch * KCHUNK3;
        __syncthreads();
        {
            float4* bd = (float4*)baps;
            for (int i = t; i < 64 * 32; i += 128) {
                const int bb = i >> 5, k4 = i & 31;
                bd[bb * 33 + k4] =
                    *(const float4*)(g_bap + (size_t)bb * KTOT + kb + 4 * k4);
            }
            float4* wd = (float4*)wcs;
            for (int i = t; i < 64 * 32; i += 128) {
                const int r = i >> 5, k4 = i & 31;
                const int n = n0 + r;
                float4 v = make_float4(0.f, 0.f, 0.f, 0.f);
                if (n < NC)
                    v = *(const float4*)(Wc + (size_t)n * KTOT + kb + 4 * k4);
                wd[r * 33 + k4] = v;
            }
        }
        __syncthreads();

        const ulonglong2* bu = (const ulonglong2*)baps;  // row stride 33 u2
        const ulonglong2* wu = (const ulonglong2*)wcs;

#pragma unroll 4
        for (int k4 = 0; k4 < 32; ++k4) {
            ulonglong2 w[4];
#pragma unroll
            for (int j = 0; j < 4; ++j)
                w[j] = wu[(ng + 16 * j) * 33 + k4];
#pragma unroll
            for (int i = 0; i < 8; ++i) {
                const ulonglong2 bv = bu[(bg + 8 * i) * 33 + k4];
#pragma unroll
                for (int j = 0; j < 4; ++j) {
                    fma2(acc[i][j], bv.x, w[j].x);
                    fma2(acc[i][j], bv.y, w[j].y);
                }
            }
        }
    }

#pragma unroll
    for (int i = 0; i < 8; ++i) {
        const int b = bg + 8 * i;
#pragma unroll
        for (int j = 0; j < 4; ++j) {
            const int n = n0 + ng + 16 * j;
            if (n < NC)
                g_part3[((size_t)ks * BB + b) * NC + n] = red2(acc[i][j]);
        }
    }
}

// ============================================================================
// Kernel 3b: reduce K-split partials + bias -> out [64][396].
// ============================================================================
__global__ __launch_bounds__(256) void k3_reduce(const float* __restrict__ bc,
                                                 float* __restrict__ out) {
    const int i = blockIdx.x * 256 + threadIdx.x;   // exactly 25344 threads
    const int n = i % NC;
    float s = bc[n];
#pragma unroll
    for (int j = 0; j < KS3; ++j)
        s += g_part3[(size_t)j * (BB * NC) + i];
    out[i] = s;
}

// ============================================================================
extern "C" void kernel_launch(void* const* d_in, const int* in_sizes, int n_in,
                              void* d_out, int out_size) {
    const float* x  = (const float*)d_in[0];
    const float* Wa = (const float*)d_in[1];
    const float* ba = (const float*)d_in[2];
    const float* Wc = (const float*)d_in[3];
    const float* bc = (const float*)d_in[4];
    float* out = (float*)d_out;

    const int smem_k1 = CSLICE * 32 * (int)sizeof(unsigned long long); // 65536 B
    const int smem_k2 = (64 * HW + 32 * HW) * (int)sizeof(float);      // 75264 B
    const int smem_k3 = (2 * 64 * 132) * (int)sizeof(float);           // 67584 B
    cudaFuncSetAttribute(k1_logits, cudaFuncAttributeMaxDynamicSharedMemorySize, smem_k1);
    cudaFuncSetAttribute(k2_bap,    cudaFuncAttributeMaxDynamicSharedMemorySize, smem_k2);
    cudaFuncSetAttribute(k3_gemm,   cudaFuncAttributeMaxDynamicSharedMemorySize, smem_k3);

    k1_logits<<<dim3(BB, KS1), 224, smem_k1>>>(x, Wa);
    k1b_sigmoid<<<(BB * MM * HW) / 256, 256>>>(ba);
    k2_bap<<<dim3(CC / 64, BB), 128, smem_k2>>>(x);
    k3_gemm<<<dim3(KS3, NT3), 128, smem_k3>>>(Wc);
    k3_reduce<<<(BB * NC) / 256, 256>>>(bc, out);

    (void)in_sizes; (void)n_in; (void)out_size;
}

// round 5
// speedup vs baseline: 1.2654x; 1.2654x over previous
#include <cuda_runtime.h>
#include <cuda_bf16.h>
#include <math.h>

// Problem constants
#define BB   64
#define CC   2048
#define HW   196
#define MM   32
#define NC   396
#define KTOT (MM * CC)          // 65536

// kernel-1 split-K
#define KS1     8
#define CSLICE  (CC / KS1)      // 256

// kernel-3 split-K
#define KS3       64
#define KSLICE3   (KTOT / KS3)  // 1024
#define KCHUNK3   64
#define NTILE3    64
#define NT3       7             // ceil(396/64)

// -------- scratch (device globals; no runtime allocation) --------
__device__ float g_part1[KS1 * BB * MM * HW];     // 12.85 MB: [ks][b][m][hw]
__device__ float g_A    [BB * MM * HW];           //  1.6 MB : [b][m][hw]
__device__ float g_bap  [BB * KTOT];              // 16.0 MB : [b][m*2048+c]
__device__ float g_part3[KS3 * BB * NC];          //  6.5 MB : [ks][b][n]

// -------- packed f32x2 helpers (Blackwell FFMA2 path) --------
__device__ __forceinline__ unsigned long long pk2(float lo, float hi) {
    unsigned long long r;
    asm("mov.b64 %0, {%1, %2};" : "=l"(r) : "f"(lo), "f"(hi));
    return r;
}
__device__ __forceinline__ void fma2(unsigned long long& d,
                                     unsigned long long a,
                                     unsigned long long b) {
    asm("fma.rn.f32x2 %0, %1, %2, %0;" : "+l"(d) : "l"(a), "l"(b));
}
__device__ __forceinline__ float red2(unsigned long long v) {
    float lo, hi;
    asm("mov.b64 {%0, %1}, %2;" : "=f"(lo), "=f"(hi) : "l"(v));
    return lo + hi;
}

// ============================================================================
// Kernel 1 (R2 version — measured good): partial attention logits.
// grid (BB, KS1), block 224 (thread = hw, 196 active).
// Wa chunk staged in smem PRE-PACKED as {w[m],w[m+1]} pairs so an LDS.128
// (warp-uniform broadcast) yields two ready f32x2 operands.
// ============================================================================
__global__ __launch_bounds__(224) void k1_logits(const float* __restrict__ x,
                                                 const float* __restrict__ Wa) {
    __shared__ float ws[16 * 16 * 4];

    const int b  = blockIdx.x;
    const int ks = blockIdx.y;
    const int t  = threadIdx.x;
    const int hw = t;

    unsigned long long acc[32];
#pragma unroll
    for (int m = 0; m < 32; ++m) acc[m] = 0ull;

    const float* xb = x + (size_t)b * CC * HW;

    for (int cc = 0; cc < CSLICE; cc += 32) {
        const int c0 = ks * CSLICE + cc;
        __syncthreads();
        for (int idx = t; idx < 512; idx += 224) {
            const int m  = idx >> 4;
            const int j2 = idx & 15;
            const float2 w = *(const float2*)(Wa + (size_t)m * CC + c0 + 2 * j2);
            float* dst = ws + (j2 * 16 + (m >> 1)) * 4 + (m & 1) * 2;
            dst[0] = w.x; dst[1] = w.y;
        }
        __syncthreads();

        if (hw < HW) {
            const ulonglong2* wsu = (const ulonglong2*)ws;
#pragma unroll
            for (int j2 = 0; j2 < 16; ++j2) {
                const float* xp = xb + (size_t)(c0 + 2 * j2) * HW + hw;
                const unsigned long long xv = pk2(xp[0], xp[HW]);
#pragma unroll
                for (int m2 = 0; m2 < 16; ++m2) {
                    const ulonglong2 w = wsu[j2 * 16 + m2];
                    fma2(acc[2 * m2],     xv, w.x);
                    fma2(acc[2 * m2 + 1], xv, w.y);
                }
            }
        }
    }

    if (hw < HW) {
        const size_t base = ((size_t)ks * BB + b) * (MM * HW) + hw;
#pragma unroll
        for (int m = 0; m < 32; ++m)
            g_part1[base + (size_t)m * HW] = red2(acc[m]);
    }
}

// ============================================================================
// Kernel 1b: reduce split-K partials, add bias, sigmoid -> g_A.
// ============================================================================
__global__ __launch_bounds__(256) void k1b_sigmoid(const float* __restrict__ ba) {
    const int i = blockIdx.x * 256 + threadIdx.x;
    const int m = (i / HW) & (MM - 1);
    float z = ba[m];
#pragma unroll
    for (int s = 0; s < KS1; ++s)
        z += g_part1[(size_t)s * (BB * MM * HW) + i];
    g_A[i] = 1.0f / (1.0f + expf(-z));
}

// ============================================================================
// Kernel 2 (R2 version — measured good): BAP pooling.
// grid (32 c-tiles, 64 b), block 128. Thread tile: 2c x 8m, hw-packed f32x2.
// ============================================================================
__global__ __launch_bounds__(128) void k2_bap(const float* __restrict__ x) {
    extern __shared__ float sm2[];
    float* xs  = sm2;                 // [64][196]
    float* as_ = sm2 + 64 * HW;       // [32][196]

    const int b  = blockIdx.y;
    const int c0 = blockIdx.x * 64;
    const int t  = threadIdx.x;

    {
        const float4* xsrc = (const float4*)(x + ((size_t)b * CC + c0) * HW);
        float4* xd = (float4*)xs;
        for (int i = t; i < 64 * (HW / 4); i += 128) xd[i] = xsrc[i];
        const float4* asrc = (const float4*)(g_A + (size_t)b * (MM * HW));
        float4* ad = (float4*)as_;
        for (int i = t; i < 32 * (HW / 4); i += 128) ad[i] = asrc[i];
    }
    __syncthreads();

    const int cp = t & 31;    // c = c0 + cp and c0 + cp + 32
    const int g  = t >> 5;    // m base = g*8

    unsigned long long acc[2][8];
#pragma unroll
    for (int i = 0; i < 2; ++i)
#pragma unroll
        for (int j = 0; j < 8; ++j) acc[i][j] = 0ull;

    const ulonglong2* xu = (const ulonglong2*)xs;   // row stride 49 u2
    const ulonglong2* au = (const ulonglong2*)as_;

#pragma unroll 7
    for (int h4 = 0; h4 < HW / 4; ++h4) {
        const ulonglong2 xa = xu[cp * 49 + h4];
        const ulonglong2 xb = xu[(cp + 32) * 49 + h4];
#pragma unroll
        for (int mm = 0; mm < 8; ++mm) {
            const ulonglong2 a = au[(g * 8 + mm) * 49 + h4];
            fma2(acc[0][mm], xa.x, a.x);
            fma2(acc[0][mm], xa.y, a.y);
            fma2(acc[1][mm], xb.x, a.x);
            fma2(acc[1][mm], xb.y, a.y);
        }
    }

    const float inv = 1.0f / 196.0f;
#pragma unroll
    for (int i = 0; i < 2; ++i) {
        const int c = c0 + cp + i * 32;
#pragma unroll
        for (int mm = 0; mm < 8; ++mm) {
            const int m = g * 8 + mm;
            g_bap[(size_t)b * KTOT + (size_t)m * CC + c] = red2(acc[i][mm]) * inv;
        }
    }
}

// ============================================================================
// Kernel 3: classifier GEMM partials. grid (KS3, NT3), block 128.
// Tile 64b x 64n, thread tile 8b x 4n (n = n0 + ng + 16j):
//   per k4: 12 LDS.128 (all single-phase) vs 64 fma2.
// KCHUNK=64 -> smem 34.8 KB; __launch_bounds__(128,4) caps regs so 4 blocks
// (16 warps, 50% occ) stay resident — fixes the R4 occ=17.5% stall.
// ============================================================================
__global__ __launch_bounds__(128, 4) void k3_gemm(const float* __restrict__ Wc) {
    extern __shared__ float sm3[];
    float* baps = sm3;                 // [64][68]
    float* wcs  = sm3 + 64 * 68;       // [64][68]

    const int ks = blockIdx.x;
    const int n0 = blockIdx.y * NTILE3;
    const int t  = threadIdx.x;
    const int bg = t & 7;
    const int ng = t >> 3;             // 0..15, n = n0 + ng + 16*j

    unsigned long long acc[8][4];
#pragma unroll
    for (int i = 0; i < 8; ++i)
#pragma unroll
        for (int j = 0; j < 4; ++j) acc[i][j] = 0ull;

    const size_t kbase0 = (size_t)ks * KSLICE3;

    for (int ch = 0; ch < KSLICE3 / KCHUNK3; ++ch) {
        const size_t kb = kbase0 + (size_t)ch * KCHUNK3;
        __syncthreads();
        {
            float4* bd = (float4*)baps;
            for (int i = t; i < 64 * 16; i += 128) {
                const int bb = i >> 4, k4 = i & 15;
                bd[bb * 17 + k4] =
                    *(const float4*)(g_bap + (size_t)bb * KTOT + kb + 4 * k4);
            }
            float4* wd = (float4*)wcs;
            for (int i = t; i < 64 * 16; i += 128) {
                const int r = i >> 4, k4 = i & 15;
                const int n = n0 + r;
                float4 v = make_float4(0.f, 0.f, 0.f, 0.f);
                if (n < NC)
                    v = *(const float4*)(Wc + (size_t)n * KTOT + kb + 4 * k4);
                wd[r * 17 + k4] = v;
            }
        }
        __syncthreads();

        const ulonglong2* bu = (const ulonglong2*)baps;  // row stride 17 u2
        const ulonglong2* wu = (const ulonglong2*)wcs;

#pragma unroll 4
        for (int k4 = 0; k4 < 16; ++k4) {
            ulonglong2 w[4];
#pragma unroll
            for (int j = 0; j < 4; ++j)
                w[j] = wu[(ng + 16 * j) * 17 + k4];
#pragma unroll
            for (int i = 0; i < 8; ++i) {
                const ulonglong2 bv = bu[(bg + 8 * i) * 17 + k4];
#pragma unroll
                for (int j = 0; j < 4; ++j) {
                    fma2(acc[i][j], bv.x, w[j].x);
                    fma2(acc[i][j], bv.y, w[j].y);
                }
            }
        }
    }

#pragma unroll
    for (int i = 0; i < 8; ++i) {
        const int b = bg + 8 * i;
#pragma unroll
        for (int j = 0; j < 4; ++j) {
            const int n = n0 + ng + 16 * j;
            if (n < NC)
                g_part3[((size_t)ks * BB + b) * NC + n] = red2(acc[i][j]);
        }
    }
}

// ============================================================================
// Kernel 3b: reduce K-split partials + bias -> out [64][396].
// ============================================================================
__global__ __launch_bounds__(256) void k3_reduce(const float* __restrict__ bc,
                                                 float* __restrict__ out) {
    const int i = blockIdx.x * 256 + threadIdx.x;   // exactly 25344 threads
    const int n = i % NC;
    float s = bc[n];
#pragma unroll
    for (int j = 0; j < KS3; ++j)
        s += g_part3[(size_t)j * (BB * NC) + i];
    out[i] = s;
}

// ============================================================================
extern "C" void kernel_launch(void* const* d_in, const int* in_sizes, int n_in,
                              void* d_out, int out_size) {
    const float* x  = (const float*)d_in[0];
    const float* Wa = (const float*)d_in[1];
    const float* ba = (const float*)d_in[2];
    const float* Wc = (const float*)d_in[3];
    const float* bc = (const float*)d_in[4];
    float* out = (float*)d_out;

    const int smem_k2 = (64 * HW + 32 * HW) * (int)sizeof(float);   // 75264 B
    const int smem_k3 = (2 * 64 * 68) * (int)sizeof(float);         // 34816 B
    cudaFuncSetAttribute(k2_bap,  cudaFuncAttributeMaxDynamicSharedMemorySize, smem_k2);
    cudaFuncSetAttribute(k3_gemm, cudaFuncAttributeMaxDynamicSharedMemorySize, smem_k3);

    k1_logits<<<dim3(BB, KS1), 224>>>(x, Wa);
    k1b_sigmoid<<<(BB * MM * HW) / 256, 256>>>(ba);
    k2_bap<<<dim3(CC / 64, BB), 128, smem_k2>>>(x);
    k3_gemm<<<dim3(KS3, NT3), 128, smem_k3>>>(Wc);
    k3_reduce<<<(BB * NC) / 256, 256>>>(bc, out);

    (void)in_sizes; (void)n_in; (void)out_size;
}